// round 1
// baseline (speedup 1.0000x reference)
#include <cuda_runtime.h>

#define RPB 256          // rows per block
#define NCOLS 14
#define IN_F4 (RPB * NCOLS / 4)   // 896 float4 per block
#define OUT_F4 (RPB * 3 / 4)      // 192 float4 per block

__global__ __launch_bounds__(256, 8)
void indicator_kernel(const float* __restrict__ in, float* __restrict__ out, int n) {
    __shared__ float s_in[RPB * NCOLS];   // 14336 B
    __shared__ float s_out[RPB * 3];      // 3072 B

    const int tid = threadIdx.x;
    const long long row0 = (long long)blockIdx.x * RPB;

    // ---- coalesced vectorized load: 256 contiguous rows -> smem ----
    {
        const float4* __restrict__ in4 = (const float4*)in;
        float4* s4 = (float4*)s_in;
        const long long f4base  = row0 * NCOLS / 4;           // divisible: 3584*bid/4
        const long long f4total = (long long)n * NCOLS / 4;   // 28M/4 exactly
        #pragma unroll
        for (int k = tid; k < IN_F4; k += 256) {
            long long g = f4base + k;
            if (g < f4total) s4[k] = in4[g];
        }
    }
    __syncthreads();

    // ---- per-row compute ----
    const long long row = row0 + tid;
    if (row < n) {
        const float* r = &s_in[tid * NCOLS];
        const float ha_open  = r[0];
        const float ha_close = r[1];
        const float lw       = r[5];
        const float uw       = r[6];
        const float ma       = r[8];
        const float srsi     = r[9];
        const float ssig     = r[10];
        const float bu       = r[11];
        const float bm       = r[12];
        const float bl       = r[13];

        const bool  bullish = ha_close > ha_open;
        const bool  bearish = ha_close < ha_open;
        const float body    = fabsf(ha_close - ha_open);
        const bool  sb = bullish && (body > 0.5f) && (uw < 1e-6f);  // strong_bullish
        const bool  sB = bearish && (body > 0.5f) && (lw < 1e-6f);  // strong_bearish

        const float ha2 = sb ? 0.8f : 0.0f;
        const float ha0 = sB ? 0.8f : 0.0f;

        const float width = (bu - bl) / bm;
        const float pp    = (ha_close - bl) / (bu - bl);
        // squeeze & expansion is structurally always false, kept for fidelity:
        const bool  sqexp = (width < 0.1f) && (width > 0.2f);
        const float sqf   = sqexp ? 0.9f : 0.0f;

        const bool pp_lo = pp < 0.2f;
        const bool pp_hi = pp > 0.8f;
        const float bb2 = (pp_lo ? 0.8f : 0.0f) + sqf;
        const float bb0 = (pp_hi ? 0.8f : 0.0f) + sqf;

        const float st2 = (srsi < 0.2f) ? 0.8f : 0.0f;
        const float st0 = (srsi > 0.8f) ? 0.8f : 0.0f;

        const bool  ma_up = ma > 0.1f;
        const bool  ma_dn = ma < -0.1f;
        const float ma2 = ma_up ? 0.7f : 0.0f;
        const float ma0 = ma_dn ? 0.7f : 0.0f;

        const bool st_dn = ssig < -0.1f;
        const bool st_up = ssig > 0.1f;

        // OR of all 3-of-4 conjunctions == majority(>=3 of 4)
        const bool long_sig  = ((int)sb + (int)ma_up + (int)st_dn + (int)pp_lo) >= 3;
        const bool short_sig = ((int)sB + (int)ma_dn + (int)st_up + (int)pp_hi) >= 3;

        const float hms2 = long_sig  ? 0.9f : 0.0f;
        const float hms0 = short_sig ? 0.9f : 0.0f;

        const float col0 = ha0 + ma0 + st0 + bb0 + 2.0f * hms0;
        const float col2 = ha2 + ma2 + st2 + bb2 + 2.0f * hms2;
        const float col1 = 1.5f;

        const float m  = fmaxf(fmaxf(col0, col2), col1);
        const float e0 = __expf(col0 - m);
        const float e1 = __expf(col1 - m);
        const float e2 = __expf(col2 - m);
        const float inv = 1.0f / (e0 + e1 + e2);

        s_out[tid * 3 + 0] = e0 * inv;
        s_out[tid * 3 + 1] = e1 * inv;
        s_out[tid * 3 + 2] = e2 * inv;
    }
    __syncthreads();

    // ---- coalesced vectorized store ----
    {
        float4* __restrict__ o4 = (float4*)out;
        const float4* so4 = (const float4*)s_out;
        const long long o4base  = row0 * 3 / 4;            // 192*bid
        const long long o4total = (long long)n * 3 / 4;    // 6M/4 exactly
        #pragma unroll
        for (int k = tid; k < OUT_F4; k += 256) {
            long long g = o4base + k;
            if (g < o4total) o4[g] = so4[k];
        }
    }
}

extern "C" void kernel_launch(void* const* d_in, const int* in_sizes, int n_in,
                              void* d_out, int out_size) {
    const float* state = (const float*)d_in[0];
    float* out = (float*)d_out;
    const int n = in_sizes[0] / NCOLS;     // 2,000,000 rows
    const int grid = (n + RPB - 1) / RPB;  // 7813 blocks
    indicator_kernel<<<grid, 256>>>(state, out, n);
}